// round 6
// baseline (speedup 1.0000x reference)
#include <cuda_runtime.h>
#include <cstdint>

#define Bq 4
#define T 128
#define D 300
#define D4 75            // D / 4 (float4 count per row)
#define KSPLIT 152       // k-split boundary (multiple of 8)

// Projection partials + final q|k|v scratch
__device__ __align__(16) float g_part0[3 * Bq * T * D];
__device__ __align__(16) float g_part1[3 * Bq * T * D];
__device__ __align__(16) float g_qkv [3 * Bq * T * D];

// ---- cp.async helpers -------------------------------------------------------
__device__ __forceinline__ uint32_t smem_u32(const void* p) {
    return (uint32_t)__cvta_generic_to_shared(p);
}
#define CP_ASYNC16(dst_u32, src_ptr) \
    asm volatile("cp.async.cg.shared.global [%0], [%1], 16;" \
                 :: "r"(dst_u32), "l"(src_ptr) : "memory")
#define CP_COMMIT() asm volatile("cp.async.commit_group;" ::: "memory")
#define CP_WAIT1()  asm volatile("cp.async.wait_group 1;" ::: "memory")
#define CP_WAIT0()  asm volatile("cp.async.wait_group 0;" ::: "memory")

// ---------------------------------------------------------------------------
// Kernel 1: projection GEMM, 2-way k-split for occupancy.
// partial[r,c] = sum_{k in half} A[r,k] * W[c,k]  (+bias in half 0)
// 32x64 tiles, 128 threads, 4x4 microtile, double-buffered k-chunks of 32.
// Grid (5, 48, 2): 480 CTAs.
// ---------------------------------------------------------------------------
__global__ __launch_bounds__(128) void proj_kernel(
    const float* __restrict__ query, const float* __restrict__ key,
    const float* __restrict__ value,
    const float* __restrict__ WQ, const float* __restrict__ bQ,
    const float* __restrict__ WK, const float* __restrict__ bK)
{
    __shared__ float A_s[2][32][36];
    __shared__ float W_s[2][32][68];

    const int row0 = blockIdx.y * 32;
    const int col0 = blockIdx.x * 64;
    const int kh   = blockIdx.z;          // 0 or 1
    const int ks   = kh ? KSPLIT : 0;
    const int ke   = kh ? D : KSPLIT;
    float* outp    = kh ? g_part1 : g_part0;

    const int tid  = threadIdx.x;
    const int tx   = tid & 15;    // 16 col groups x 4
    const int ty   = tid >> 4;    // 8 row groups x 4

    const int sel = row0 >> 9;    // 0: query, 1: key, 2: value
    const float* Ap = (sel == 0) ? query : (sel == 1 ? key : value);
    const float* Wp = (sel == 0) ? WQ : WK;
    const float* bp = (sel == 0) ? bQ : bK;
    const int arow0 = row0 & 511;

    const int NC = (ke - ks + 31) / 32;   // 5 chunks in both halves
    float4 a_r[2], w_r[4];

    auto fetch = [&](int k0) {
#pragma unroll
        for (int p = 0; p < 2; p++) {
            int idx = p * 128 + tid;
            int ar = idx & 31, kk = k0 + ((idx >> 5) << 2);
            a_r[p] = (kk + 4 <= ke) ? *(const float4*)&Ap[(arow0 + ar) * D + kk]
                                    : make_float4(0.f, 0.f, 0.f, 0.f);
        }
#pragma unroll
        for (int p = 0; p < 4; p++) {
            int idx = p * 128 + tid;
            int wr = idx & 63, kk = k0 + ((idx >> 6) << 2);
            int gc = col0 + wr;
            w_r[p] = (kk + 4 <= ke && gc < D) ? *(const float4*)&Wp[gc * D + kk]
                                              : make_float4(0.f, 0.f, 0.f, 0.f);
        }
    };
    auto store = [&](int buf) {
#pragma unroll
        for (int p = 0; p < 2; p++) {
            int idx = p * 128 + tid;
            int ar = idx & 31, e = (idx >> 5) << 2;
            A_s[buf][e + 0][ar] = a_r[p].x; A_s[buf][e + 1][ar] = a_r[p].y;
            A_s[buf][e + 2][ar] = a_r[p].z; A_s[buf][e + 3][ar] = a_r[p].w;
        }
#pragma unroll
        for (int p = 0; p < 4; p++) {
            int idx = p * 128 + tid;
            int wr = idx & 63, e = (idx >> 6) << 2;
            W_s[buf][e + 0][wr] = w_r[p].x; W_s[buf][e + 1][wr] = w_r[p].y;
            W_s[buf][e + 2][wr] = w_r[p].z; W_s[buf][e + 3][wr] = w_r[p].w;
        }
    };

    float acc[4][4];
#pragma unroll
    for (int r = 0; r < 4; r++)
#pragma unroll
        for (int c = 0; c < 4; c++) acc[r][c] = 0.f;

    fetch(ks);
    store(0);
    __syncthreads();

    for (int ch = 0; ch < NC; ch++) {
        const int buf = ch & 1;
        if (ch + 1 < NC) fetch(ks + (ch + 1) * 32);
#pragma unroll
        for (int e = 0; e < 32; e++) {
            float4 av = *(const float4*)&A_s[buf][e][ty * 4];
            float4 wv = *(const float4*)&W_s[buf][e][tx * 4];
            float a4[4] = {av.x, av.y, av.z, av.w};
            float w4[4] = {wv.x, wv.y, wv.z, wv.w};
#pragma unroll
            for (int r = 0; r < 4; r++)
#pragma unroll
                for (int c = 0; c < 4; c++) acc[r][c] += a4[r] * w4[c];
        }
        if (ch + 1 < NC) store(1 - buf);
        __syncthreads();
    }

#pragma unroll
    for (int r = 0; r < 4; r++) {
        int gr = row0 + ty * 4 + r;
#pragma unroll
        for (int c = 0; c < 4; c++) {
            int gcol = col0 + tx * 4 + c;
            if (gcol < D)
                outp[gr * D + gcol] = acc[r][c] + (kh ? 0.f : bp[gcol]);
        }
    }
}

// ---------------------------------------------------------------------------
// Kernel 1b: sum the two k-split partials. 115200 float4 = 450 x 256.
// ---------------------------------------------------------------------------
__global__ __launch_bounds__(256) void reduce_kernel()
{
    int idx = blockIdx.x * 256 + threadIdx.x;
    float4 x = ((const float4*)g_part0)[idx];
    float4 y = ((const float4*)g_part1)[idx];
    ((float4*)g_qkv)[idx] = make_float4(x.x + y.x, x.y + y.y, x.z + y.z, x.w + y.w);
}

// ---------------------------------------------------------------------------
// Kernel 2: fused attention, cp.async 3-stage pipeline.
// One CTA per (b, i), 256 threads, 4 CTAs/SM (single wave).
// Stage = 4 j-rows x {hL, hR, k} = 12 rows x 1200B = 14.4KB; 2 stages in
// flight per CTA -> ~115KB/SM outstanding loads (register-free MLP).
// ---------------------------------------------------------------------------
__global__ __launch_bounds__(256, 4) void attn_kernel(
    const float* __restrict__ hL, const float* __restrict__ hR,
    float* __restrict__ out)
{
    __shared__ float4 buf_s[3][12][75];   // [stage][row: 0-3 hL,4-7 hR,8-11 k][c]
    __shared__ float  q_s[304];
    __shared__ float  sc2[128][2];
    __shared__ float  attn_s[128];

    const int tid  = threadIdx.x;
    const int lane = tid & 31;
    const int w    = tid >> 5;           // 8 warps
    const int b    = blockIdx.x >> 7;
    const int i    = blockIdx.x & 127;

    const float4* qkv4 = (const float4*)g_qkv;
    const float4* hL4  = (const float4*)hL + ((size_t)(b * T + i)) * T * D4;
    const float4* hRb  = (const float4*)hR + ((size_t)b * T * T + i) * D4;
    const float4* k4b  = qkv4 + (Bq * T + b * T) * D4;

    const uint32_t buf_base = smem_u32(&buf_s[0][0][0]);

    // q_i (L2-hot) — ready by the barrier at the top of the first stage.
    if (tid < D4) ((float4*)q_s)[tid] = qkv4[(b * T + i) * D4 + tid];

    // ---- async stage issue: 900 x 16B per stage ----
    auto issue = [&](int s) {
        const int jb = s * 4;
        const uint32_t dst0 = buf_base + (uint32_t)((s % 3) * 12 * 75 * 16);
#pragma unroll
        for (int p = 0; p < 4; p++) {
            int o = p * 256 + tid;
            if (o < 900) {
                int r = o / 75;
                int c = o - r * 75;
                const float4* src;
                if (r < 4)      src = hL4 + (size_t)(jb + r) * D4 + c;
                else if (r < 8) src = hRb + (size_t)(jb + r - 4) * T * D4 + c;
                else            src = k4b + (jb + r - 8) * D4 + c;
                CP_ASYNC16(dst0 + (uint32_t)(r * 75 + c) * 16, src);
            }
        }
    };

    issue(0); CP_COMMIT();
    issue(1); CP_COMMIT();

    const int jl   = w >> 1;      // 0..3 : j within stage
    const int half = w & 1;       // d-range half

    for (int s = 0; s < 32; s++) {
        if (s < 31) { CP_WAIT1(); } else { CP_WAIT0(); }
        __syncthreads();

        // ---- compute stage s: 2 warps per j ----
        {
            const float4* L = &buf_s[s % 3][jl][0];
            const float4* R = &buf_s[s % 3][4 + jl][0];
            const float4* K = &buf_s[s % 3][8 + jl][0];
            const float4* q4 = (const float4*)q_s;

            int c = half * 32 + lane;
            float4 l = L[c], r = R[c], kk = K[c], qq = q4[c];
            float acc = (qq.x + l.x) * (kk.x + r.x) + (qq.y + l.y) * (kk.y + r.y)
                      + (qq.z + l.z) * (kk.z + r.z) + (qq.w + l.w) * (kk.w + r.w);
            if (half && lane < D4 - 64) {          // c2 = 64..74
                int c2 = 64 + lane;
                float4 l2 = L[c2], r2 = R[c2], k2 = K[c2], q2 = q4[c2];
                acc += (q2.x + l2.x) * (k2.x + r2.x) + (q2.y + l2.y) * (k2.y + r2.y)
                     + (q2.z + l2.z) * (k2.z + r2.z) + (q2.w + l2.w) * (k2.w + r2.w);
            }
#pragma unroll
            for (int o = 16; o > 0; o >>= 1)
                acc += __shfl_xor_sync(0xffffffffu, acc, o);
            if (lane == 0) sc2[s * 4 + jl][half] = acc;
        }

        if (s + 2 < 32) issue(s + 2);
        CP_COMMIT();   // empty group on tail iterations keeps wait semantics
    }
    __syncthreads();

    // ---- p = softmax(scores); attn = softmax(1000*p); clip is a no-op.
    // p_max = 1/sum exactly (max exp term is 1): 1000*(p-p_max) = 1000*inv*(e-1)
    if (w == 0) {
        float s0 = sc2[lane][0]      + sc2[lane][1];
        float s1 = sc2[lane + 32][0] + sc2[lane + 32][1];
        float s2 = sc2[lane + 64][0] + sc2[lane + 64][1];
        float s3 = sc2[lane + 96][0] + sc2[lane + 96][1];
        float m = fmaxf(fmaxf(s0, s1), fmaxf(s2, s3));
#pragma unroll
        for (int o = 16; o > 0; o >>= 1)
            m = fmaxf(m, __shfl_xor_sync(0xffffffffu, m, o));
        float e0 = expf(s0 - m), e1 = expf(s1 - m);
        float e2 = expf(s2 - m), e3 = expf(s3 - m);
        float sum = e0 + e1 + e2 + e3;
#pragma unroll
        for (int o = 16; o > 0; o >>= 1)
            sum += __shfl_xor_sync(0xffffffffu, sum, o);
        float inv = 1.f / sum;
        float a0 = expf(1000.f * inv * (e0 - 1.f));
        float a1 = expf(1000.f * inv * (e1 - 1.f));
        float a2 = expf(1000.f * inv * (e2 - 1.f));
        float a3 = expf(1000.f * inv * (e3 - 1.f));
        float sum2 = a0 + a1 + a2 + a3;
#pragma unroll
        for (int o = 16; o > 0; o >>= 1)
            sum2 += __shfl_xor_sync(0xffffffffu, sum2, o);
        float inv2 = 1.f / sum2;
        attn_s[lane]      = a0 * inv2;
        attn_s[lane + 32] = a1 * inv2;
        attn_s[lane + 64] = a2 * inv2;
        attn_s[lane + 96] = a3 * inv2;
    }
    __syncthreads();

    // ---- output: out[b,i,d] = sum_j attn_j * (v[b,j,d] + hR[b,j,i,d])
    // attn is near-one-hot after x1000 sharpening: skip negligible j.
    const float* vg  = g_qkv + (size_t)(2 * Bq * T + b * T) * D;
    const float* hRs = hR + ((size_t)b * T * T + i) * D;
#pragma unroll
    for (int rep = 0; rep < 2; rep++) {
        int d = tid + rep * 256;
        if (d < D) {
            float acc = 0.f;
            for (int j = 0; j < T; j++) {
                float a = attn_s[j];
                if (a > 1e-12f)
                    acc += a * (vg[j * D + d] + hRs[(size_t)j * T * D + d]);
            }
            out[(b * T + i) * D + d] = acc;
        }
    }
}

// ---------------------------------------------------------------------------
extern "C" void kernel_launch(void* const* d_in, const int* in_sizes, int n_in,
                              void* d_out, int out_size)
{
    const float* query = (const float*)d_in[0];
    const float* key   = (const float*)d_in[1];
    const float* value = (const float*)d_in[2];
    const float* hL    = (const float*)d_in[3];
    const float* hR    = (const float*)d_in[4];
    const float* WQ    = (const float*)d_in[5];
    const float* bQ    = (const float*)d_in[6];
    const float* WK    = (const float*)d_in[7];
    const float* bK    = (const float*)d_in[8];
    float* out = (float*)d_out;

    proj_kernel<<<dim3(5, 48, 2), 128>>>(query, key, value, WQ, bQ, WK, bK);
    reduce_kernel<<<450, 256>>>();
    attn_kernel<<<Bq * T, 256>>>(hL, hR, out);
}